// round 4
// baseline (speedup 1.0000x reference)
#include <cuda_runtime.h>
#include <cstdint>

#define BATCH 32
#define SEQ   2048
#define DIM   256
#define HID   512
#define GATES 2048
#define OUTD  256
#define ROWS  (BATCH * SEQ)
#define NCTA  128

// ------------------------- static device scratch ---------------------------
__device__ float g_xg[(size_t)SEQ * BATCH * GATES];   // [t][b][cp] 536 MB
__device__ float g_hs[(size_t)ROWS * HID];            // [b*SEQ+t][j] 134 MB
__device__ float g_WxP[DIM * GATES];
__device__ float g_WhT[GATES * HID];                  // [cp][k]
__device__ float g_bP[GATES];
__device__ float g_h[2 * BATCH * HID];                // double-buffered hidden
__device__ unsigned long long g_bar;                  // monotonic ticket

// ---------------------------------------------------------------------------
// Phase 0: permute weights (cp = 4*j + gate; original col c = gate*512 + j)
// and zero both h buffers.
// ---------------------------------------------------------------------------
__global__ void prep_kernel(const float* __restrict__ Wx,
                            const float* __restrict__ Wh,
                            const float* __restrict__ b) {
    int tid = blockIdx.x * blockDim.x + threadIdx.x;
    int nt  = gridDim.x * blockDim.x;
    for (int i = tid; i < GATES * HID; i += nt) {
        int cp = i / HID, k = i % HID;
        int c  = (cp & 3) * HID + (cp >> 2);
        g_WhT[i] = Wh[k * GATES + c];
    }
    for (int i = tid; i < DIM * GATES; i += nt) {
        int cp = i % GATES;
        int c  = (cp & 3) * HID + (cp >> 2);
        g_WxP[i] = Wx[(i / GATES) * GATES + c];
    }
    for (int i = tid; i < GATES; i += nt) {
        int c = (i & 3) * HID + (i >> 2);
        g_bP[i] = b[c];
    }
    for (int i = tid; i < 2 * BATCH * HID; i += nt) g_h[i] = 0.f;
}

// ---------------------------------------------------------------------------
// Phases 1 & 3: fp32 SIMT GEMM 128x128 tile, BK=8, 256 thr, 8x8 microtile.
// REMAP: input row r=(b*SEQ+s) writes to output row (s*BATCH+b).
// All dims divide tiles exactly.
// ---------------------------------------------------------------------------
template <bool REMAP, bool BIAS>
__global__ __launch_bounds__(256)
void sgemm128(const float* __restrict__ A, const float* __restrict__ B,
              float* __restrict__ C, const float* __restrict__ bias,
              int K, int N) {
    __shared__ float As[8][128];
    __shared__ float Bs[8][128];
    const int tid  = threadIdx.x;
    const int tx   = tid & 15;
    const int ty   = tid >> 4;
    const int aRow = tid >> 1;
    const int aCol = (tid & 1) * 4;
    const int bRow = tid >> 5;
    const int bCol = (tid & 31) * 4;

    const float* Ag = A + (size_t)blockIdx.y * 128 * K;
    const float* Bg = B + blockIdx.x * 128;

    float acc[8][8];
#pragma unroll
    for (int i = 0; i < 8; i++)
#pragma unroll
        for (int j = 0; j < 8; j++) acc[i][j] = 0.f;

    for (int k0 = 0; k0 < K; k0 += 8) {
        float4 av = *(const float4*)(Ag + (size_t)aRow * K + k0 + aCol);
        float4 bv = *(const float4*)(Bg + (size_t)(k0 + bRow) * N + bCol);
        __syncthreads();
        As[aCol + 0][aRow] = av.x;
        As[aCol + 1][aRow] = av.y;
        As[aCol + 2][aRow] = av.z;
        As[aCol + 3][aRow] = av.w;
        *(float4*)&Bs[bRow][bCol] = bv;
        __syncthreads();
#pragma unroll
        for (int kk = 0; kk < 8; kk++) {
            float ar[8], br[8];
            *(float4*)(ar)     = *(const float4*)&As[kk][ty * 8];
            *(float4*)(ar + 4) = *(const float4*)&As[kk][ty * 8 + 4];
            *(float4*)(br)     = *(const float4*)&Bs[kk][tx * 8];
            *(float4*)(br + 4) = *(const float4*)&Bs[kk][tx * 8 + 4];
#pragma unroll
            for (int i = 0; i < 8; i++)
#pragma unroll
                for (int j = 0; j < 8; j++)
                    acc[i][j] = fmaf(ar[i], br[j], acc[i][j]);
        }
    }

    float bv8[8];
    if (BIAS) {
        const float* bp = bias + blockIdx.x * 128 + tx * 8;
#pragma unroll
        for (int j = 0; j < 8; j++) bv8[j] = bp[j];
    }
#pragma unroll
    for (int i = 0; i < 8; i++) {
        int r = blockIdx.y * 128 + ty * 8 + i;
        size_t orow = REMAP ? ((size_t)(r & (SEQ - 1)) * BATCH + (size_t)(r >> 11))
                            : (size_t)r;
        float* cp = C + orow * N + blockIdx.x * 128 + tx * 8;
        float4 v0, v1;
        v0.x = acc[i][0]; v0.y = acc[i][1]; v0.z = acc[i][2]; v0.w = acc[i][3];
        v1.x = acc[i][4]; v1.y = acc[i][5]; v1.z = acc[i][6]; v1.w = acc[i][7];
        if (BIAS) {
            v0.x += bv8[0]; v0.y += bv8[1]; v0.z += bv8[2]; v0.w += bv8[3];
            v1.x += bv8[4]; v1.y += bv8[5]; v1.z += bv8[6]; v1.w += bv8[7];
        }
        *(float4*)cp       = v0;
        *(float4*)(cp + 4) = v1;
    }
}

// ---------------------------------------------------------------------------
// Phase 2: persistent recurrence. 128 CTAs x 256 thr.
// CTA cta owns hidden units j = 4*cta..4*cta+3 (permuted cols 16*cta..+15).
// Warp wgp handles cols 2*wgp, 2*wgp+1; lane kl covers k = 64*q + 2*kl + {0,1}.
// ---------------------------------------------------------------------------
__device__ __forceinline__ void grid_sync() {
    __syncthreads();
    if (threadIdx.x == 0) {
        __threadfence();
        unsigned long long t = atomicAdd(&g_bar, 1ull) + 1ull;
        unsigned long long target = ((t + (NCTA - 1)) / NCTA) * NCTA;
        while (*((volatile unsigned long long*)&g_bar) < target) {
            __nanosleep(32);   // gentle backoff: don't hammer L2 at one address
        }
        __threadfence();
    }
    __syncthreads();
}

__device__ __forceinline__ float sigm(float x) { return 1.f / (1.f + __expf(-x)); }

__global__ __launch_bounds__(256, 1)
void lstm_kernel() {
    extern __shared__ float sm[];
    float* h_sh    = sm;                         // [32][512]
    float* gate_sh = sm + BATCH * HID;           // [16][32]  (col, b)
    float* c_sh    = gate_sh + 16 * BATCH;       // [128]

    const int tid = threadIdx.x;
    const int cta = blockIdx.x;
    const int wgp = tid >> 5;
    const int kl  = tid & 31;

    // weight-stationary Wh slice: 32 regs/thread
    float w0[16], w1[16];
    {
        const float* p0 = g_WhT + (size_t)(16 * cta + 2 * wgp) * HID;
        const float* p1 = p0 + HID;
#pragma unroll
        for (int q = 0; q < 8; q++) {
            float2 a = *(const float2*)(p0 + 64 * q + 2 * kl);
            float2 c = *(const float2*)(p1 + 64 * q + 2 * kl);
            w0[2 * q] = a.x; w0[2 * q + 1] = a.y;
            w1[2 * q] = c.x; w1[2 * q + 1] = c.y;
        }
    }

    float4 bias4 = make_float4(0.f, 0.f, 0.f, 0.f);
    if (tid < 128) {
        bias4 = *(const float4*)(g_bP + 16 * cta + 4 * (tid >> 5));
        c_sh[tid] = 0.f;
    }

    for (int t = 0; t < SEQ; t++) {
        // load h(t) into shared
        const float* hsrc = g_h + (t & 1) * BATCH * HID;
        for (int i = tid; i < BATCH * HID / 4; i += 256)
            *(float4*)&h_sh[i * 4] = *(const float4*)&hsrc[i * 4];
        __syncthreads();

        // h @ Wh slice
        float a0[32], a1[32];
#pragma unroll
        for (int b = 0; b < 32; b++) { a0[b] = 0.f; a1[b] = 0.f; }
#pragma unroll
        for (int q = 0; q < 8; q++) {
            const int off = 64 * q + 2 * kl;
#pragma unroll
            for (int b = 0; b < 32; b++) {
                float2 hv = *(const float2*)&h_sh[b * HID + off];
                a0[b] = fmaf(hv.x, w0[2 * q], a0[b]);
                a0[b] = fmaf(hv.y, w0[2 * q + 1], a0[b]);
                a1[b] = fmaf(hv.x, w1[2 * q], a1[b]);
                a1[b] = fmaf(hv.y, w1[2 * q + 1], a1[b]);
            }
        }

        // cross-lane reduce, lane 0 writes gates
#pragma unroll
        for (int b = 0; b < 32; b++) {
            float v0 = a0[b], v1 = a1[b];
#pragma unroll
            for (int s = 16; s; s >>= 1) {
                v0 += __shfl_xor_sync(0xFFFFFFFFu, v0, s);
                v1 += __shfl_xor_sync(0xFFFFFFFFu, v1, s);
            }
            if (kl == 0) {
                gate_sh[(2 * wgp) * 32 + b]     = v0;
                gate_sh[(2 * wgp + 1) * 32 + b] = v1;
            }
        }
        __syncthreads();

        // pointwise LSTM update (tid<128): jl = tid>>5, b = tid&31
        if (tid < 128) {
            const int jl = tid >> 5, b = tid & 31;
            float4 xv = *(const float4*)(g_xg + ((size_t)t * BATCH + b) * GATES
                                         + 16 * cta + 4 * jl);
            float gi = gate_sh[(4 * jl + 0) * 32 + b] + xv.x + bias4.x;
            float gf = gate_sh[(4 * jl + 1) * 32 + b] + xv.y + bias4.y;
            float gg = gate_sh[(4 * jl + 2) * 32 + b] + xv.z + bias4.z;
            float go = gate_sh[(4 * jl + 3) * 32 + b] + xv.w + bias4.w;
            float c = sigm(gf) * c_sh[tid] + sigm(gi) * tanhf(gg);
            c_sh[tid] = c;
            float h = sigm(go) * tanhf(c);
            int j = 4 * cta + jl;
            g_h[((t + 1) & 1) * BATCH * HID + b * HID + j] = h;
            g_hs[((size_t)b * SEQ + t) * HID + j] = h;
        }
        grid_sync();
    }
}

// ---------------------------------------------------------------------------
extern "C" void kernel_launch(void* const* d_in, const int* in_sizes, int n_in,
                              void* d_out, int out_size) {
    const float* x  = (const float*)d_in[0];
    const float* Wx = (const float*)d_in[1];
    const float* Wh = (const float*)d_in[2];
    const float* b  = (const float*)d_in[3];
    const float* Wo = (const float*)d_in[4];
    const float* bo = (const float*)d_in[5];
    float* y = (float*)d_out;

    cudaFuncSetAttribute(lstm_kernel,
                         cudaFuncAttributeMaxDynamicSharedMemorySize,
                         (BATCH * HID + 16 * BATCH + 128) * 4);

    prep_kernel<<<256, 256>>>(Wx, Wh, b);

    // Phase 1: xg[t][b][cp] = x @ WxP   (M=65536, N=2048, K=256), t-major remap
    {
        float* xg0;  cudaGetSymbolAddress((void**)&xg0, g_xg);
        float* wxp;  cudaGetSymbolAddress((void**)&wxp, g_WxP);
        dim3 grid(GATES / 128, ROWS / 128);
        sgemm128<true, false><<<grid, 256>>>(x, wxp, xg0, nullptr, DIM, GATES);
    }

    // Phase 2: recurrence
    lstm_kernel<<<NCTA, 256, (BATCH * HID + 16 * BATCH + 128) * 4>>>();

    // Phase 3: y = hs @ Wo + bo   (M=65536, N=256, K=512)
    {
        float* hs0;  cudaGetSymbolAddress((void**)&hs0, g_hs);
        dim3 grid(OUTD / 128, ROWS / 128);
        sgemm128<false, true><<<grid, 256>>>(hs0, Wo, y, bo, HID, OUTD);
    }
}

// round 6
// speedup vs baseline: 1.4351x; 1.4351x over previous
#include <cuda_runtime.h>
#include <cuda_fp16.h>
#include <cstdint>

#define BATCH 32
#define SEQ   2048
#define DIM   256
#define HID   512
#define GATES 2048
#define OUTD  256
#define ROWS  (BATCH * SEQ)
#define NCTA  128

// ------------------------- static device scratch ---------------------------
__device__ float  g_xg[(size_t)SEQ * BATCH * GATES];   // [t][b][cp]
__device__ float  g_hs[(size_t)ROWS * HID];            // [b*SEQ+t][j]
__device__ float  g_WxP[DIM * GATES];
__device__ float  g_WhT[GATES * HID];                  // [cp][k]
__device__ float  g_bP[GATES];
__device__ __half g_hh[2 * BATCH * HID];               // fp16 recurrent h, dbl-buf
__device__ unsigned long long g_bar;                   // monotonic ticket

// ---------------------------------------------------------------------------
// Phase 0: permute weights (cp = 4*j + gate; original col c = gate*512 + j),
// zero fp16 h buffers.
// ---------------------------------------------------------------------------
__global__ void prep_kernel(const float* __restrict__ Wx,
                            const float* __restrict__ Wh,
                            const float* __restrict__ b) {
    int tid = blockIdx.x * blockDim.x + threadIdx.x;
    int nt  = gridDim.x * blockDim.x;
    for (int i = tid; i < GATES * HID; i += nt) {
        int cp = i / HID, k = i % HID;
        int c  = (cp & 3) * HID + (cp >> 2);
        g_WhT[i] = Wh[k * GATES + c];
    }
    for (int i = tid; i < DIM * GATES; i += nt) {
        int cp = i % GATES;
        int c  = (cp & 3) * HID + (cp >> 2);
        g_WxP[i] = Wx[(i / GATES) * GATES + c];
    }
    for (int i = tid; i < GATES; i += nt) {
        int c = (i & 3) * HID + (i >> 2);
        g_bP[i] = b[c];
    }
    unsigned* hz = (unsigned*)g_hh;                    // 2*32*512 halves = 16384 u32
    for (int i = tid; i < BATCH * HID; i += nt) hz[i] = 0u;
}

// ---------------------------------------------------------------------------
// Phases 1 & 3: fp32 SIMT GEMM 128x128 tile, BK=8, 256 thr, 8x8 microtile.
// ---------------------------------------------------------------------------
template <bool REMAP, bool BIAS>
__global__ __launch_bounds__(256)
void sgemm128(const float* __restrict__ A, const float* __restrict__ B,
              float* __restrict__ C, const float* __restrict__ bias,
              int K, int N) {
    __shared__ float As[8][128];
    __shared__ float Bs[8][128];
    const int tid  = threadIdx.x;
    const int tx   = tid & 15;
    const int ty   = tid >> 4;
    const int aRow = tid >> 1;
    const int aCol = (tid & 1) * 4;
    const int bRow = tid >> 5;
    const int bCol = (tid & 31) * 4;

    const float* Ag = A + (size_t)blockIdx.y * 128 * K;
    const float* Bg = B + blockIdx.x * 128;

    float acc[8][8];
#pragma unroll
    for (int i = 0; i < 8; i++)
#pragma unroll
        for (int j = 0; j < 8; j++) acc[i][j] = 0.f;

    for (int k0 = 0; k0 < K; k0 += 8) {
        float4 av = *(const float4*)(Ag + (size_t)aRow * K + k0 + aCol);
        float4 bv = *(const float4*)(Bg + (size_t)(k0 + bRow) * N + bCol);
        __syncthreads();
        As[aCol + 0][aRow] = av.x;
        As[aCol + 1][aRow] = av.y;
        As[aCol + 2][aRow] = av.z;
        As[aCol + 3][aRow] = av.w;
        *(float4*)&Bs[bRow][bCol] = bv;
        __syncthreads();
#pragma unroll
        for (int kk = 0; kk < 8; kk++) {
            float ar[8], br[8];
            *(float4*)(ar)     = *(const float4*)&As[kk][ty * 8];
            *(float4*)(ar + 4) = *(const float4*)&As[kk][ty * 8 + 4];
            *(float4*)(br)     = *(const float4*)&Bs[kk][tx * 8];
            *(float4*)(br + 4) = *(const float4*)&Bs[kk][tx * 8 + 4];
#pragma unroll
            for (int i = 0; i < 8; i++)
#pragma unroll
                for (int j = 0; j < 8; j++)
                    acc[i][j] = fmaf(ar[i], br[j], acc[i][j]);
        }
    }

    float bv8[8];
    if (BIAS) {
        const float* bp = bias + blockIdx.x * 128 + tx * 8;
#pragma unroll
        for (int j = 0; j < 8; j++) bv8[j] = bp[j];
    }
#pragma unroll
    for (int i = 0; i < 8; i++) {
        int r = blockIdx.y * 128 + ty * 8 + i;
        size_t orow = REMAP ? ((size_t)(r & (SEQ - 1)) * BATCH + (size_t)(r >> 11))
                            : (size_t)r;
        float* cp = C + orow * N + blockIdx.x * 128 + tx * 8;
        float4 v0, v1;
        v0.x = acc[i][0]; v0.y = acc[i][1]; v0.z = acc[i][2]; v0.w = acc[i][3];
        v1.x = acc[i][4]; v1.y = acc[i][5]; v1.z = acc[i][6]; v1.w = acc[i][7];
        if (BIAS) {
            v0.x += bv8[0]; v0.y += bv8[1]; v0.z += bv8[2]; v0.w += bv8[3];
            v1.x += bv8[4]; v1.y += bv8[5]; v1.z += bv8[6]; v1.w += bv8[7];
        }
        *(float4*)cp       = v0;
        *(float4*)(cp + 4) = v1;
    }
}

// ---------------------------------------------------------------------------
// Phase 2 helpers
// ---------------------------------------------------------------------------
__device__ __forceinline__ unsigned long long ffma2(unsigned long long a,
                                                    unsigned long long b,
                                                    unsigned long long c) {
    unsigned long long d;
    asm("fma.rn.f32x2 %0, %1, %2, %3;" : "=l"(d) : "l"(a), "l"(b), "l"(c));
    return d;
}
__device__ __forceinline__ float2 upk(unsigned long long v) {
    float2 r;
    asm("mov.b64 {%0, %1}, %2;" : "=f"(r.x), "=f"(r.y) : "l"(v));
    return r;
}

// Butterfly transpose-reduce: 8 values per lane (index i), summed across the
// 32 lanes. Lane kl (kl&3==0) ends up holding the total for index kl>>2.
__device__ __forceinline__ float bfly8(float v0, float v1, float v2, float v3,
                                       float v4, float v5, float v6, float v7,
                                       int lane) {
    bool hi = lane & 16;
    float s0 = hi ? v0 : v4, s1 = hi ? v1 : v5, s2 = hi ? v2 : v6, s3 = hi ? v3 : v7;
    float r0 = __shfl_xor_sync(~0u, s0, 16), r1 = __shfl_xor_sync(~0u, s1, 16);
    float r2 = __shfl_xor_sync(~0u, s2, 16), r3 = __shfl_xor_sync(~0u, s3, 16);
    float t0 = (hi ? v4 : v0) + r0, t1 = (hi ? v5 : v1) + r1;
    float t2 = (hi ? v6 : v2) + r2, t3 = (hi ? v7 : v3) + r3;
    bool h2 = lane & 8;
    float p0 = h2 ? t0 : t2, p1 = h2 ? t1 : t3;
    float q0 = __shfl_xor_sync(~0u, p0, 8), q1 = __shfl_xor_sync(~0u, p1, 8);
    float u0 = (h2 ? t2 : t0) + q0, u1 = (h2 ? t3 : t1) + q1;
    bool h3 = lane & 4;
    float ss = h3 ? u0 : u1;
    float rr = __shfl_xor_sync(~0u, ss, 4);
    float w  = (h3 ? u1 : u0) + rr;
    w += __shfl_xor_sync(~0u, w, 2);
    w += __shfl_xor_sync(~0u, w, 1);
    return w;
}

__device__ __forceinline__ void grid_sync() {
    __syncthreads();
    if (threadIdx.x == 0) {
        __threadfence();
        unsigned long long t = atomicAdd(&g_bar, 1ull) + 1ull;
        unsigned long long target = ((t + (NCTA - 1)) / NCTA) * NCTA;
        while (*((volatile unsigned long long*)&g_bar) < target) {}
        __threadfence();
    }
    __syncthreads();
}

__device__ __forceinline__ float sigm(float x) { return 1.f / (1.f + __expf(-x)); }

// ---------------------------------------------------------------------------
// Phase 2: persistent recurrence. 128 CTAs x 256 thr.
// Warps 0-3: compute. Warp wgp owns permuted cols 4*wgp..4*wgp+3 = all 4
//   gates of hidden unit jl = wgp. Lane kl covers k = 4*kl + 128*q + {0..3}.
// Warps 4-7: pointwise LSTM update (thread = (unit jl, batch pb)).
// ---------------------------------------------------------------------------
__global__ __launch_bounds__(256, 1)
void lstm_kernel() {
    extern __shared__ float sm[];
    float* h_sh    = sm;                       // [32][512] fp32, 64 KB
    float* gate_sh = sm + BATCH * HID;         // [16][33]

    const int tid = threadIdx.x;
    const int cta = blockIdx.x;
    const int wgp = tid >> 5;
    const int kl  = tid & 31;

    // weight-stationary Wh slice, pre-packed as f32x2 pairs (b64 loads)
    unsigned long long wA[4][4], wB[4][4];
    if (wgp < 4) {
#pragma unroll
        for (int cw = 0; cw < 4; cw++) {
            const float* base = g_WhT + (size_t)(16 * cta + 4 * wgp + cw) * HID;
#pragma unroll
            for (int q = 0; q < 4; q++) {
                int k = 4 * kl + 128 * q;
                wA[cw][q] = *(const unsigned long long*)(base + k);
                wB[cw][q] = *(const unsigned long long*)(base + k + 2);
            }
        }
    }

    float4 bias4 = make_float4(0.f, 0.f, 0.f, 0.f);
    float4 xv_next = make_float4(0.f, 0.f, 0.f, 0.f);
    float  creg = 0.f;
    if (tid >= 128) {
        const int jl = (tid - 128) >> 5, pb = (tid - 128) & 31;
        bias4   = *(const float4*)(g_bP + 16 * cta + 4 * jl);
        xv_next = *(const float4*)(g_xg + (size_t)pb * GATES + 16 * cta + 4 * jl);
    }

    for (int t = 0; t < SEQ; t++) {
        // ---- broadcast h(t): fp16 global -> fp32 smem (32 KB -> 64 KB) ----
        const uint2* src = (const uint2*)(g_hh + (size_t)(t & 1) * BATCH * HID);
#pragma unroll
        for (int r = 0; r < 16; r++) {
            int f = r * 256 + tid;                       // float4 index, 0..4095
            uint2 hraw = src[f];
            float2 f0 = __half22float2(*(__half2*)&hraw.x);
            float2 f1 = __half22float2(*(__half2*)&hraw.y);
            ((float4*)h_sh)[f] = make_float4(f0.x, f0.y, f1.x, f1.y);
        }
        __syncthreads();

        if (wgp < 4) {
            // ---- h @ Wh slice: packed f32x2 FMA, 4 cols, b in chunks of 8 ----
#pragma unroll
            for (int ch = 0; ch < 4; ch++) {
                unsigned long long acc[4][8];
#pragma unroll
                for (int cw = 0; cw < 4; cw++)
#pragma unroll
                    for (int i = 0; i < 8; i++) acc[cw][i] = 0ull;
#pragma unroll
                for (int q = 0; q < 4; q++) {
#pragma unroll
                    for (int i = 0; i < 8; i++) {
                        const ulonglong2 hv = *(const ulonglong2*)
                            &h_sh[(ch * 8 + i) * HID + 128 * q + 4 * kl];
#pragma unroll
                        for (int cw = 0; cw < 4; cw++) {
                            acc[cw][i] = ffma2(hv.x, wA[cw][q], acc[cw][i]);
                            acc[cw][i] = ffma2(hv.y, wB[cw][q], acc[cw][i]);
                        }
                    }
                }
#pragma unroll
                for (int cw = 0; cw < 4; cw++) {
                    float s[8];
#pragma unroll
                    for (int i = 0; i < 8; i++) {
                        float2 p = upk(acc[cw][i]);
                        s[i] = p.x + p.y;
                    }
                    float tot = bfly8(s[0], s[1], s[2], s[3],
                                      s[4], s[5], s[6], s[7], kl);
                    if ((kl & 3) == 0)
                        gate_sh[(4 * wgp + cw) * 33 + ch * 8 + (kl >> 2)] = tot;
                }
            }
        }
        __syncthreads();

        // ---- pointwise LSTM update (warps 4-7) ----
        if (tid >= 128) {
            const int jl = (tid - 128) >> 5, pb = (tid - 128) & 31;
            float4 xv = xv_next;
            if (t + 1 < SEQ)
                xv_next = *(const float4*)(g_xg + ((size_t)(t + 1) * BATCH + pb) * GATES
                                           + 16 * cta + 4 * jl);
            float gi = gate_sh[(4 * jl + 0) * 33 + pb] + xv.x + bias4.x;
            float gf = gate_sh[(4 * jl + 1) * 33 + pb] + xv.y + bias4.y;
            float gg = gate_sh[(4 * jl + 2) * 33 + pb] + xv.z + bias4.z;
            float go = gate_sh[(4 * jl + 3) * 33 + pb] + xv.w + bias4.w;
            float c = sigm(gf) * creg + sigm(gi) * tanhf(gg);
            creg = c;
            float h = sigm(go) * tanhf(c);
            int j = 4 * cta + jl;
            g_hs[((size_t)pb * SEQ + t) * HID + j] = h;
            g_hh[(size_t)((t + 1) & 1) * BATCH * HID + pb * HID + j] =
                __float2half_rn(h);
        }
        grid_sync();
    }
}

// ---------------------------------------------------------------------------
extern "C" void kernel_launch(void* const* d_in, const int* in_sizes, int n_in,
                              void* d_out, int out_size) {
    const float* x  = (const float*)d_in[0];
    const float* Wx = (const float*)d_in[1];
    const float* Wh = (const float*)d_in[2];
    const float* b  = (const float*)d_in[3];
    const float* Wo = (const float*)d_in[4];
    const float* bo = (const float*)d_in[5];
    float* y = (float*)d_out;

    const int lstm_smem = (BATCH * HID + 16 * 33) * 4;   // 67648 B
    cudaFuncSetAttribute(lstm_kernel,
                         cudaFuncAttributeMaxDynamicSharedMemorySize, lstm_smem);

    prep_kernel<<<256, 256>>>(Wx, Wh, b);

    // Phase 1: xg[t][b][cp] = x @ WxP   (M=65536, N=2048, K=256), t-major remap
    {
        float* xg0;  cudaGetSymbolAddress((void**)&xg0, g_xg);
        float* wxp;  cudaGetSymbolAddress((void**)&wxp, g_WxP);
        dim3 grid(GATES / 128, ROWS / 128);
        sgemm128<true, false><<<grid, 256>>>(x, wxp, xg0, nullptr, DIM, GATES);
    }

    // Phase 2: recurrence
    lstm_kernel<<<NCTA, 256, lstm_smem>>>();

    // Phase 3: y = hs @ Wo + bo   (M=65536, N=256, K=512)
    {
        float* hs0;  cudaGetSymbolAddress((void**)&hs0, g_hs);
        dim3 grid(OUTD / 128, ROWS / 128);
        sgemm128<false, true><<<grid, 256>>>(hs0, Wo, y, bo, HID, OUTD);
    }
}